// round 2
// baseline (speedup 1.0000x reference)
#include <cuda_runtime.h>
#include <cuda_bf16.h>
#include <cstdint>

#define NN 6144
#define IN_DIM 512
#define CHANNELS 4
#define C_DIM 64
#define FDIM 256          // CHANNELS * C_DIM
#define CAP 128           // max neighbors per row (mean ~31, sd ~5.5)

#define BUILD_BLOCKS (NN / 8)            // 768
#define PROJ_TILES   (NN / 128)          // 48
#define PROJ_BLOCKS  (PROJ_TILES * 4)    // 192

// -------- scratch (device globals; no allocation allowed) --------
__device__ float g_featsA[(size_t)NN * FDIM];
__device__ float g_featsB[(size_t)NN * FDIM];
__device__ int   g_ell[(size_t)NN * CAP];
__device__ int   g_deg[NN];

#define FMA2(d, a, b, c) \
    asm("fma.rn.f32x2 %0, %1, %2, %3;" : "=l"(d) : "l"(a), "l"(b), "l"(c))
#define PACK2(d, x) \
    asm("mov.b64 %0, {%1, %2};" : "=l"(d) : "f"(x), "f"(x))
#define UNPACK2(lo, hi, s) \
    asm("mov.b64 {%0, %1}, %2;" : "=f"(lo), "=f"(hi) : "l"(s))

// ============================================================
// Fused kernel 1: (a) dense adj -> ELL (warp/row, int4 + 4-ballot,
// order-preserving) and (b) feats0 = l2norm(features@W + b) with
// f32x2 packed FFMA, 128x64 tile, 8x4 microtile. Independent work,
// dispatched by blockIdx range so DRAM-bound (a) overlaps FMA-bound (b).
// ============================================================
__global__ __launch_bounds__(256) void prep_kernel(const int* __restrict__ adj,
                                                   const float* __restrict__ feat,
                                                   const float* __restrict__ W,
                                                   const float* __restrict__ bias) {
    __shared__ float sA[16][128];
    __shared__ float sB[16][64];

    if (blockIdx.x < BUILD_BLOCKS) {
        // ---------------- ELL build ----------------
        int row = blockIdx.x * 8 + (threadIdx.x >> 5);
        int lane = threadIdx.x & 31;
        const int4* arow = (const int4*)(adj + (size_t)row * NN);
        unsigned lt = (1u << lane) - 1u;
        int total = 0;
        int* erow = g_ell + (size_t)row * CAP;
        for (int it = 0; it < NN / 128; it++) {
            int4 v = arow[it * 32 + lane];
            bool p0 = v.x > 0, p1 = v.y > 0, p2 = v.z > 0, p3 = v.w > 0;
            unsigned b0 = __ballot_sync(0xffffffffu, p0);
            unsigned b1 = __ballot_sync(0xffffffffu, p1);
            unsigned b2 = __ballot_sync(0xffffffffu, p2);
            unsigned b3 = __ballot_sync(0xffffffffu, p3);
            int basec = __popc(b0 & lt) + __popc(b1 & lt) + __popc(b2 & lt) + __popc(b3 & lt);
            int idx0 = it * 128 + lane * 4;
            int pos = total + basec;
            if (p0) { if (pos < CAP) erow[pos] = idx0; pos++; }
            if (p1) { if (pos < CAP) erow[pos] = idx0 + 1; pos++; }
            if (p2) { if (pos < CAP) erow[pos] = idx0 + 2; pos++; }
            if (p3) { if (pos < CAP) erow[pos] = idx0 + 3; }
            total += __popc(b0) + __popc(b1) + __popc(b2) + __popc(b3);
        }
        if (lane == 0) g_deg[row] = total < CAP ? total : CAP;
        return;
    }

    // ---------------- projection ----------------
    const int pb = blockIdx.x - BUILD_BLOCKS;
    const int c  = pb & 3;
    const int n0 = (pb >> 2) * 128;
    const int t  = threadIdx.x;
    const int tx = t & 15;          // col group: cols tx*4 .. +4
    const int ty = t >> 4;          // row group: rows ty*8 .. +8

    unsigned long long acc2[4][4];  // [row-pair][col], packed f32x2
#pragma unroll
    for (int i = 0; i < 4; i++)
#pragma unroll
        for (int j = 0; j < 4; j++) acc2[i][j] = 0ull;

    const float* Wc = W + (size_t)c * IN_DIM * C_DIM;
    const int lrow = t >> 1, lseg = t & 1;  // A loader: row, d-half
    const int bld  = t >> 4, blk  = t & 15; // B loader

    for (int d0 = 0; d0 < IN_DIM; d0 += 16) {
        const float* fr = feat + (size_t)(n0 + lrow) * IN_DIM + d0 + lseg * 8;
        float4 av0 = *(const float4*)fr;
        float4 av1 = *(const float4*)(fr + 4);
        sA[lseg * 8 + 0][lrow] = av0.x;
        sA[lseg * 8 + 1][lrow] = av0.y;
        sA[lseg * 8 + 2][lrow] = av0.z;
        sA[lseg * 8 + 3][lrow] = av0.w;
        sA[lseg * 8 + 4][lrow] = av1.x;
        sA[lseg * 8 + 5][lrow] = av1.y;
        sA[lseg * 8 + 6][lrow] = av1.z;
        sA[lseg * 8 + 7][lrow] = av1.w;
        *(float4*)&sB[bld][blk * 4] = *(const float4*)(Wc + (size_t)(d0 + bld) * C_DIM + blk * 4);
        __syncthreads();
#pragma unroll
        for (int dd = 0; dd < 16; dd++) {
            unsigned long long ap[4];
#pragma unroll
            for (int i = 0; i < 4; i++)
                ap[i] = *(const unsigned long long*)&sA[dd][ty * 8 + 2 * i];
            float4 bq = *(const float4*)&sB[dd][tx * 4];
            unsigned long long bp[4];
            PACK2(bp[0], bq.x);
            PACK2(bp[1], bq.y);
            PACK2(bp[2], bq.z);
            PACK2(bp[3], bq.w);
#pragma unroll
            for (int i = 0; i < 4; i++)
#pragma unroll
                for (int j = 0; j < 4; j++)
                    FMA2(acc2[i][j], ap[i], bp[j], acc2[i][j]);
        }
        __syncthreads();
    }

    // unpack, bias, per-row L2 norm (row spans 16 tx lanes x 4 cols)
    float r[8][4];
#pragma unroll
    for (int i = 0; i < 4; i++)
#pragma unroll
        for (int j = 0; j < 4; j++)
            UNPACK2(r[2 * i][j], r[2 * i + 1][j], acc2[i][j]);

    float4 bb4 = *(const float4*)(bias + c * C_DIM + tx * 4);
    float bb[4] = {bb4.x, bb4.y, bb4.z, bb4.w};
#pragma unroll
    for (int i = 0; i < 8; i++) {
        float ss = 0.f;
#pragma unroll
        for (int j = 0; j < 4; j++) {
            r[i][j] += bb[j];
            ss += r[i][j] * r[i][j];
        }
        ss += __shfl_xor_sync(0xffffffffu, ss, 1);
        ss += __shfl_xor_sync(0xffffffffu, ss, 2);
        ss += __shfl_xor_sync(0xffffffffu, ss, 4);
        ss += __shfl_xor_sync(0xffffffffu, ss, 8);
        float sc = rsqrtf(fmaxf(ss, 1e-24f));
        float4 o = make_float4(r[i][0] * sc, r[i][1] * sc, r[i][2] * sc, r[i][3] * sc);
        *(float4*)(g_featsA + (size_t)(n0 + ty * 8 + i) * FDIM + c * C_DIM + tx * 4) = o;
    }
}

// ============================================================
// Kernel 2: one attention+aggregate+renorm iteration.
// Warp per node: 32 lanes x 8 floats = one full 256-float row.
// No smem, no barriers; neighbor loads software-pipelined.
// ============================================================
__global__ __launch_bounds__(128) void iterate_kernel(int pass, float* __restrict__ d_final) {
    const float* __restrict__ src = (pass == 1) ? g_featsB : g_featsA;
    float* __restrict__ dst = (pass == 0) ? g_featsB : (pass == 1) ? g_featsA : d_final;

    const int w = threadIdx.x >> 5, lane = threadIdx.x & 31;
    const int n = blockIdx.x * 4 + w;

    const float* xrow = src + (size_t)n * FDIM + lane * 8;
    float4 x0 = *(const float4*)xrow;
    float4 x1 = *(const float4*)(xrow + 4);
    float4 a0 = make_float4(0.f, 0.f, 0.f, 0.f);
    float4 a1 = make_float4(0.f, 0.f, 0.f, 0.f);

    const int d = g_deg[n];
    const int* erow = g_ell + (size_t)n * CAP;
    int mycol = erow[lane];

    float4 ya0, ya1;
    if (d > 0) {
        int m0 = __shfl_sync(0xffffffffu, mycol, 0);
        const float* yr = src + (size_t)m0 * FDIM + lane * 8;
        ya0 = *(const float4*)yr;
        ya1 = *(const float4*)(yr + 4);
    }

    for (int i = 0; i < d; i++) {
        // prefetch neighbor i+1 (uniform control across warp)
        float4 yb0, yb1;
        int inext = i + 1;
        if (inext < d) {
            int b = inext & 31;
            if (b == 0) mycol = erow[inext + lane];
            int mn = __shfl_sync(0xffffffffu, mycol, b);
            const float* yr = src + (size_t)mn * FDIM + lane * 8;
            yb0 = *(const float4*)yr;
            yb1 = *(const float4*)(yr + 4);
        }

        // channel dot: reduce over my 8 floats then 8-lane group
        float p = x0.x * ya0.x + x0.y * ya0.y + x0.z * ya0.z + x0.w * ya0.w +
                  x1.x * ya1.x + x1.y * ya1.y + x1.z * ya1.z + x1.w * ya1.w;
        p += __shfl_xor_sync(0xffffffffu, p, 1);
        p += __shfl_xor_sync(0xffffffffu, p, 2);
        p += __shfl_xor_sync(0xffffffffu, p, 4);
        float s0 = p;
        float s1 = __shfl_xor_sync(0xffffffffu, s0, 8);
        float s2 = __shfl_xor_sync(0xffffffffu, s0, 16);
        float s3 = __shfl_xor_sync(0xffffffffu, s1, 16);
        // |s| <= 1 (unit rows), so no max-shift needed
        float e0 = __expf(s0);
        float e1 = __expf(s1);
        float e2 = __expf(s2);
        float e3 = __expf(s3);
        float wgt = __fdividef(e0, e0 + e1 + e2 + e3);
        a0.x += wgt * ya0.x; a0.y += wgt * ya0.y; a0.z += wgt * ya0.z; a0.w += wgt * ya0.w;
        a1.x += wgt * ya1.x; a1.y += wgt * ya1.y; a1.z += wgt * ya1.z; a1.w += wgt * ya1.w;

        ya0 = yb0; ya1 = yb1;
    }

    // self + aggregate, per-channel (8-lane group) L2 norm
    float v[8];
    v[0] = x0.x + a0.x; v[1] = x0.y + a0.y; v[2] = x0.z + a0.z; v[3] = x0.w + a0.w;
    v[4] = x1.x + a1.x; v[5] = x1.y + a1.y; v[6] = x1.z + a1.z; v[7] = x1.w + a1.w;
    float sq = 0.f;
#pragma unroll
    for (int k = 0; k < 8; k++) sq += v[k] * v[k];
    sq += __shfl_xor_sync(0xffffffffu, sq, 1);
    sq += __shfl_xor_sync(0xffffffffu, sq, 2);
    sq += __shfl_xor_sync(0xffffffffu, sq, 4);
    float sc = rsqrtf(fmaxf(sq, 1e-24f));
    float* drow = dst + (size_t)n * FDIM + lane * 8;
    *(float4*)drow       = make_float4(v[0] * sc, v[1] * sc, v[2] * sc, v[3] * sc);
    *(float4*)(drow + 4) = make_float4(v[4] * sc, v[5] * sc, v[6] * sc, v[7] * sc);
}

// ============================================================
extern "C" void kernel_launch(void* const* d_in, const int* in_sizes, int n_in,
                              void* d_out, int out_size) {
    const float* features = (const float*)d_in[0];   // [6144, 512]
    const int*   adj      = (const int*)d_in[1];     // [6144, 6144]
    const float* W        = (const float*)d_in[2];   // [4, 512, 64]
    const float* b        = (const float*)d_in[3];   // [4, 1, 64]
    float* out = (float*)d_out;                      // [6144, 256]

    prep_kernel<<<BUILD_BLOCKS + PROJ_BLOCKS, 256>>>(adj, features, W, b);
    iterate_kernel<<<NN / 4, 128>>>(0, out);
    iterate_kernel<<<NN / 4, 128>>>(1, out);
    iterate_kernel<<<NN / 4, 128>>>(2, out);
}

// round 3
// speedup vs baseline: 1.3912x; 1.3912x over previous
#include <cuda_runtime.h>
#include <cuda_bf16.h>
#include <cstdint>

#define NN 6144
#define IN_DIM 512
#define CHANNELS 4
#define C_DIM 64
#define FDIM 256          // CHANNELS * C_DIM
#define CAP 128           // max neighbors per row (mean ~31, sd ~5.5)

// -------- scratch (device globals; no allocation allowed) --------
__device__ float g_featsA[(size_t)NN * FDIM];
__device__ float g_featsB[(size_t)NN * FDIM];
__device__ int   g_ell[(size_t)NN * CAP + 64];   // +64 pad: lane-strided reads may overrun row
__device__ int   g_deg[NN];

// ============================================================
// Kernel 1: dense adj -> ELL (order-preserving, deterministic)
// one warp per row, int4 loads + 4-ballot compaction
// ============================================================
__global__ __launch_bounds__(256) void build_ell_kernel(const int* __restrict__ adj) {
    int row = blockIdx.x * 8 + (threadIdx.x >> 5);
    int lane = threadIdx.x & 31;
    const int4* arow = (const int4*)(adj + (size_t)row * NN);
    unsigned lt = (1u << lane) - 1u;
    int total = 0;
    int* erow = g_ell + (size_t)row * CAP;
    for (int it = 0; it < NN / 128; it++) {
        int4 v = arow[it * 32 + lane];
        bool p0 = v.x > 0, p1 = v.y > 0, p2 = v.z > 0, p3 = v.w > 0;
        unsigned b0 = __ballot_sync(0xffffffffu, p0);
        unsigned b1 = __ballot_sync(0xffffffffu, p1);
        unsigned b2 = __ballot_sync(0xffffffffu, p2);
        unsigned b3 = __ballot_sync(0xffffffffu, p3);
        int basec = __popc(b0 & lt) + __popc(b1 & lt) + __popc(b2 & lt) + __popc(b3 & lt);
        int idx0 = it * 128 + lane * 4;
        int pos = total + basec;
        if (p0) { if (pos < CAP) erow[pos] = idx0; pos++; }
        if (p1) { if (pos < CAP) erow[pos] = idx0 + 1; pos++; }
        if (p2) { if (pos < CAP) erow[pos] = idx0 + 2; pos++; }
        if (p3) { if (pos < CAP) erow[pos] = idx0 + 3; }
        total += __popc(b0) + __popc(b1) + __popc(b2) + __popc(b3);
    }
    if (lane == 0) g_deg[row] = total < CAP ? total : CAP;
}

// ============================================================
// Kernel 2: feats0 = l2norm(features @ W + b), layout [n][c*64+k]
// (round-1 version: 64x64 tile, 4x4 microtile, BK=16)
// ============================================================
__global__ __launch_bounds__(256) void project_kernel(const float* __restrict__ feat,
                                                      const float* __restrict__ W,
                                                      const float* __restrict__ bias) {
    __shared__ float sA[16][64];   // [d][row]
    __shared__ float sB[16][64];   // [d][k]
    __shared__ float s_scale[64];

    const int c  = blockIdx.y;
    const int n0 = blockIdx.x * 64;
    const int t  = threadIdx.x;
    const int tx = t & 15, ty = t >> 4;

    float acc[4][4];
#pragma unroll
    for (int i = 0; i < 4; i++)
#pragma unroll
        for (int j = 0; j < 4; j++) acc[i][j] = 0.f;

    const float* Wc = W + (size_t)c * IN_DIM * C_DIM;

    const int lrow = t >> 2, lseg = t & 3;   // A-tile loader mapping
    const int ld   = t >> 4, lks  = t & 15;  // B-tile loader mapping

    for (int d0 = 0; d0 < IN_DIM; d0 += 16) {
        float4 a = *(const float4*)(feat + (size_t)(n0 + lrow) * IN_DIM + d0 + lseg * 4);
        sA[lseg * 4 + 0][lrow] = a.x;
        sA[lseg * 4 + 1][lrow] = a.y;
        sA[lseg * 4 + 2][lrow] = a.z;
        sA[lseg * 4 + 3][lrow] = a.w;
        float4 bv = *(const float4*)(Wc + (size_t)(d0 + ld) * C_DIM + lks * 4);
        *(float4*)&sB[ld][lks * 4] = bv;
        __syncthreads();
#pragma unroll
        for (int d = 0; d < 16; d++) {
            float4 av = *(float4*)&sA[d][ty * 4];
            float4 bv2 = *(float4*)&sB[d][tx * 4];
            float ar[4] = {av.x, av.y, av.z, av.w};
            float br[4] = {bv2.x, bv2.y, bv2.z, bv2.w};
#pragma unroll
            for (int i = 0; i < 4; i++)
#pragma unroll
                for (int j = 0; j < 4; j++) acc[i][j] += ar[i] * br[j];
        }
        __syncthreads();
    }

    float4 bb4 = *(const float4*)(bias + c * C_DIM + tx * 4);
    float bb[4] = {bb4.x, bb4.y, bb4.z, bb4.w};
    float ss[4];
#pragma unroll
    for (int i = 0; i < 4; i++) {
        float s = 0.f;
#pragma unroll
        for (int j = 0; j < 4; j++) {
            acc[i][j] += bb[j];
            s += acc[i][j] * acc[i][j];
        }
        ss[i] = s;
    }
#pragma unroll
    for (int off = 1; off < 16; off <<= 1)
#pragma unroll
        for (int i = 0; i < 4; i++) ss[i] += __shfl_xor_sync(0xffffffffu, ss[i], off);
    if (tx == 0) {
#pragma unroll
        for (int i = 0; i < 4; i++) s_scale[ty * 4 + i] = rsqrtf(fmaxf(ss[i], 1e-24f));
    }
    __syncthreads();
#pragma unroll
    for (int i = 0; i < 4; i++) {
        float s = s_scale[ty * 4 + i];
        float4 o = make_float4(acc[i][0] * s, acc[i][1] * s, acc[i][2] * s, acc[i][3] * s);
        *(float4*)(g_featsA + (size_t)(n0 + ty * 4 + i) * FDIM + c * C_DIM + tx * 4) = o;
    }
}

// ============================================================
// Kernel 3: one attention+aggregate+renorm iteration.
// Warp per node; 4 neighbors per loop trip -> 4 independent
// shfl-reduction chains in flight. 5 shfls per neighbor:
// dot-reduce (1,2,4), then exp-sum across channels (8,16).
// ============================================================
__global__ __launch_bounds__(128) void iterate_kernel(int pass, float* __restrict__ d_final) {
    const float* __restrict__ src = (pass == 1) ? g_featsB : g_featsA;
    float* __restrict__ dst = (pass == 0) ? g_featsB : (pass == 1) ? g_featsA : d_final;

    const int w = threadIdx.x >> 5, lane = threadIdx.x & 31;
    const int n = blockIdx.x * 4 + w;

    const float* xrow = src + (size_t)n * FDIM + lane * 8;
    float4 x0 = *(const float4*)xrow;
    float4 x1 = *(const float4*)(xrow + 4);
    float4 a0 = make_float4(0.f, 0.f, 0.f, 0.f);
    float4 a1 = make_float4(0.f, 0.f, 0.f, 0.f);

    const int d = g_deg[n];
    const int* erow = g_ell + (size_t)n * CAP;
    int mycol = erow[lane];

    for (int i = 0; i < d; i += 4) {
        if ((i & 31) == 0 && i) mycol = erow[i + lane];

        // broadcast up to 4 neighbor ids (uniform across warp)
        int col[4];
        float4 y0[4], y1[4];
#pragma unroll
        for (int j = 0; j < 4; j++)
            col[j] = __shfl_sync(0xffffffffu, mycol, (i + j) & 31);
        // issue all loads up front (L2-resident rows)
#pragma unroll
        for (int j = 0; j < 4; j++) {
            if (i + j < d) {
                const float* yr = src + (size_t)col[j] * FDIM + lane * 8;
                y0[j] = *(const float4*)yr;
                y1[j] = *(const float4*)(yr + 4);
            }
        }

        // 4 independent dot/softmax chains
        float p[4], e[4], wgt[4];
#pragma unroll
        for (int j = 0; j < 4; j++) {
            if (i + j < d) {
                p[j] = x0.x * y0[j].x + x0.y * y0[j].y + x0.z * y0[j].z + x0.w * y0[j].w +
                       x1.x * y1[j].x + x1.y * y1[j].y + x1.z * y1[j].z + x1.w * y1[j].w;
            } else p[j] = 0.f;
        }
#pragma unroll
        for (int j = 0; j < 4; j++) p[j] += __shfl_xor_sync(0xffffffffu, p[j], 1);
#pragma unroll
        for (int j = 0; j < 4; j++) p[j] += __shfl_xor_sync(0xffffffffu, p[j], 2);
#pragma unroll
        for (int j = 0; j < 4; j++) p[j] += __shfl_xor_sync(0xffffffffu, p[j], 4);
        // |p| <= 1 (unit-norm channel rows): no max-shift needed
#pragma unroll
        for (int j = 0; j < 4; j++) e[j] = __expf(p[j]);
        float t[4];
#pragma unroll
        for (int j = 0; j < 4; j++) t[j] = e[j] + __shfl_xor_sync(0xffffffffu, e[j], 8);
#pragma unroll
        for (int j = 0; j < 4; j++) t[j] += __shfl_xor_sync(0xffffffffu, t[j], 16);
#pragma unroll
        for (int j = 0; j < 4; j++) wgt[j] = __fdividef(e[j], t[j]);

        // deterministic fixed-order accumulation
#pragma unroll
        for (int j = 0; j < 4; j++) {
            if (i + j < d) {
                a0.x += wgt[j] * y0[j].x; a0.y += wgt[j] * y0[j].y;
                a0.z += wgt[j] * y0[j].z; a0.w += wgt[j] * y0[j].w;
                a1.x += wgt[j] * y1[j].x; a1.y += wgt[j] * y1[j].y;
                a1.z += wgt[j] * y1[j].z; a1.w += wgt[j] * y1[j].w;
            }
        }
    }

    // self + aggregate, per-channel (8-lane group) L2 norm
    float v[8];
    v[0] = x0.x + a0.x; v[1] = x0.y + a0.y; v[2] = x0.z + a0.z; v[3] = x0.w + a0.w;
    v[4] = x1.x + a1.x; v[5] = x1.y + a1.y; v[6] = x1.z + a1.z; v[7] = x1.w + a1.w;
    float sq = 0.f;
#pragma unroll
    for (int k = 0; k < 8; k++) sq += v[k] * v[k];
    sq += __shfl_xor_sync(0xffffffffu, sq, 1);
    sq += __shfl_xor_sync(0xffffffffu, sq, 2);
    sq += __shfl_xor_sync(0xffffffffu, sq, 4);
    float sc = rsqrtf(fmaxf(sq, 1e-24f));
    float* drow = dst + (size_t)n * FDIM + lane * 8;
    *(float4*)drow       = make_float4(v[0] * sc, v[1] * sc, v[2] * sc, v[3] * sc);
    *(float4*)(drow + 4) = make_float4(v[4] * sc, v[5] * sc, v[6] * sc, v[7] * sc);
}

// ============================================================
extern "C" void kernel_launch(void* const* d_in, const int* in_sizes, int n_in,
                              void* d_out, int out_size) {
    const float* features = (const float*)d_in[0];   // [6144, 512]
    const int*   adj      = (const int*)d_in[1];     // [6144, 6144]
    const float* W        = (const float*)d_in[2];   // [4, 512, 64]
    const float* b        = (const float*)d_in[3];   // [4, 1, 64]
    float* out = (float*)d_out;                      // [6144, 256]

    build_ell_kernel<<<NN / 8, 256>>>(adj);
    project_kernel<<<dim3(NN / 64, CHANNELS), 256>>>(features, W, b);
    iterate_kernel<<<NN / 4, 128>>>(0, out);
    iterate_kernel<<<NN / 4, 128>>>(1, out);
    iterate_kernel<<<NN / 4, 128>>>(2, out);
}